// round 8
// baseline (speedup 1.0000x reference)
#include <cuda_runtime.h>

#define BB 64
#define SS 1024
#define DD 16
#define NSPLIT 4
#define TOK (BB * SS)

// Scratch (allocation-free rule: __device__ globals)
__device__ float4 g_part[NSPLIT * TOK]; // per-split partial (l, a0, a1, 0)
__device__ float2 g_q[TOK];             // q pre-scaled by 0.25*log2(e)
__device__ float4 g_kv[TOK];            // (k0,k1,v0,v1)
__device__ float  g_A[256];             // diag(g) @ (W1W2W3 + I)
__device__ float  g_csA[16];            // column sums of g_A
__device__ float  g_bA[16];             // b @ (W1W2W3+I) + bc
__device__ float  g_O[256];             // diag(g) @ Wo
__device__ float  g_csO[16];            // column sums of g_O
__device__ float  g_bO[16];             // b @ Wo + bo
__device__ unsigned int g_cnt[BB * 4];  // arrival counters (winner resets to 0)

__device__ __forceinline__ float ex2_approx(float x) {
    float y;
    asm("ex2.approx.f32 %0, %1;" : "=f"(y) : "f"(x));
    return y;
}

// ---------------------------------------------------------------------------
// Kernel 1: QKV projection (1 thread/token); block 256 does the weight folds.
// ---------------------------------------------------------------------------
__global__ void __launch_bounds__(256)
qkv_precomp_kernel(const float* __restrict__ x,
                   const float* __restrict__ Wq, const float* __restrict__ bq,
                   const float* __restrict__ Wk, const float* __restrict__ bk,
                   const float* __restrict__ Wv, const float* __restrict__ bv,
                   const float* __restrict__ W1, const float* __restrict__ b1,
                   const float* __restrict__ W2, const float* __restrict__ b2,
                   const float* __restrict__ W3, const float* __restrict__ b3,
                   const float* __restrict__ ln_g, const float* __restrict__ ln_b,
                   const float* __restrict__ Wo, const float* __restrict__ bo)
{
    int tid = threadIdx.x;

    if (blockIdx.x == TOK / 256) {
        // ------- precompute folded epilogue weights -------
        __shared__ float s1[256], s2[256], s3[256], s12[256];
        __shared__ float sA[256], sAraw[256], sO[256];
        __shared__ float sbp[16], sbc[16], sg[16], sb[16];
        int r = tid >> 4, c = tid & 15;
        s1[tid] = W1[tid]; s2[tid] = W2[tid]; s3[tid] = W3[tid];
        if (tid < 16) { sg[tid] = ln_g[tid]; sb[tid] = ln_b[tid]; }
        __syncthreads();

        float acc = 0.f;
        #pragma unroll
        for (int k = 0; k < 16; k++) acc = fmaf(s1[r*16+k], s2[k*16+c], acc);
        s12[tid] = acc;
        if (tid < 16) {                 // b1@W2 + b2
            float t = b2[tid];
            #pragma unroll
            for (int k = 0; k < 16; k++) t = fmaf(b1[k], s2[k*16+tid], t);
            sbp[tid] = t;
        }
        __syncthreads();

        float w123 = 0.f;
        #pragma unroll
        for (int k = 0; k < 16; k++) w123 = fmaf(s12[r*16+k], s3[k*16+c], w123);
        float A = w123 + (r == c ? 1.0f : 0.0f);   // residual folded in
        sAraw[tid] = A;
        sA[tid] = sg[r] * A;
        sO[tid] = sg[r] * Wo[tid];
        if (tid < 16) {                 // bc = (b1@W2+b2)@W3 + b3
            float t = b3[tid];
            #pragma unroll
            for (int k = 0; k < 16; k++) t = fmaf(sbp[k], s3[k*16+tid], t);
            sbc[tid] = t;
        }
        __syncthreads();

        g_A[tid] = sA[tid];
        g_O[tid] = sO[tid];
        if (tid < 16) {
            float cs = 0.f, bb = sbc[tid];
            float cso = 0.f, bb2 = bo[tid];
            #pragma unroll
            for (int i = 0; i < 16; i++) {
                cs  += sA[i*16+tid];
                bb   = fmaf(sb[i], sAraw[i*16+tid], bb);
                cso += sO[i*16+tid];
                bb2  = fmaf(sb[i], Wo[i*16+tid], bb2);
            }
            g_csA[tid] = cs;  g_bA[tid] = bb;
            g_csO[tid] = cso; g_bO[tid] = bb2;
        }
        return;
    }

    // ------- QKV projection -------
    __shared__ float sw[102];
    if (tid < 32)        sw[tid] = Wq[tid];
    else if (tid < 64)   sw[tid] = Wk[tid - 32];
    else if (tid < 96)   sw[tid] = Wv[tid - 64];
    else if (tid < 98)   sw[tid] = bq[tid - 96];
    else if (tid < 100)  sw[tid] = bk[tid - 98];
    else if (tid < 102)  sw[tid] = bv[tid - 100];
    __syncthreads();

    int idx = blockIdx.x * 256 + tid;
    const float4* xp = reinterpret_cast<const float4*>(x + idx * DD);
    float xv[16];
    #pragma unroll
    for (int c4 = 0; c4 < 4; c4++) {
        float4 v = xp[c4];
        xv[4*c4+0] = v.x; xv[4*c4+1] = v.y; xv[4*c4+2] = v.z; xv[4*c4+3] = v.w;
    }

    float q0 = sw[96], q1 = sw[97];
    float k0 = sw[98], k1 = sw[99];
    float v0 = sw[100], v1 = sw[101];
    #pragma unroll
    for (int i = 0; i < 16; i++) {
        float xi = xv[i];
        q0 = fmaf(xi, sw[i*2+0],    q0);
        q1 = fmaf(xi, sw[i*2+1],    q1);
        k0 = fmaf(xi, sw[32+i*2+0], k0);
        k1 = fmaf(xi, sw[32+i*2+1], k1);
        v0 = fmaf(xi, sw[64+i*2+0], v0);
        v1 = fmaf(xi, sw[64+i*2+1], v1);
    }

    const float SC = 0.25f * 1.4426950408889634f;
    g_q[idx]  = make_float2(q0 * SC, q1 * SC);
    g_kv[idx] = make_float4(k0, k1, v0, v1);
}

// ---------------------------------------------------------------------------
// Kernel 2: attention (4-way KV block split) + fused last-arriver epilogue.
// Grid (4, NSPLIT, BB), 256 threads = 256 tokens per block.
// ---------------------------------------------------------------------------
__global__ void __launch_bounds__(256)
attn_fused_kernel(const float* __restrict__ x,
                  const float* __restrict__ Wu, const float* __restrict__ bu,
                  float* __restrict__ out)
{
    __shared__ float4 skv[256];                     // KV quarter (4 KB)
    __shared__ __align__(16) float sA[256], sO[256], sWu[32];
    __shared__ float sbu[16], scsA[16], sbA[16], scsO[16], sbO[16];
    __shared__ int s_win;

    int tid   = threadIdx.x;
    int b     = blockIdx.z;
    int split = blockIdx.y;
    int chunk = blockIdx.x;
    int s     = chunk * 256 + tid;
    int idx   = b * SS + s;

    skv[tid] = g_kv[b * SS + split * 256 + tid];
    __syncthreads();

    float2 q = g_q[idx];
    float l = 0.f, a0 = 0.f, a1 = 0.f;
    #pragma unroll 8
    for (int t = 0; t < 256; t++) {
        float4 kv = skv[t];
        float d = fmaf(q.y, kv.y, q.x * kv.x);   // log2-domain score
        float p = ex2_approx(d);
        l  += p;
        a0 = fmaf(p, kv.z, a0);
        a1 = fmaf(p, kv.w, a1);
    }

    g_part[split * TOK + idx] = make_float4(l, a0, a1, 0.f);

    // ---- arrival protocol (threadFenceReduction pattern) ----
    __threadfence();
    __syncthreads();
    if (tid == 0) {
        unsigned int old = atomicAdd(&g_cnt[b * 4 + chunk], 1u);
        s_win = (old == NSPLIT - 1);
        if (s_win) g_cnt[b * 4 + chunk] = 0;   // reset for next graph replay
    }
    __syncthreads();
    if (!s_win) return;

    // ---- winner block: epilogue for its 256 tokens ----
    __threadfence();   // acquire: other splits' partials now visible

    sA[tid] = g_A[tid]; sO[tid] = g_O[tid];
    if (tid < 32) sWu[tid] = Wu[tid];
    if (tid < 16) {
        sbu[tid] = bu[tid];
        scsA[tid] = g_csA[tid]; sbA[tid] = g_bA[tid];
        scsO[tid] = g_csO[tid]; sbO[tid] = g_bO[tid];
    }

    // combine the 4 split partials (bypass L1 for cross-SM safety)
    float lt = 0.f, A0 = 0.f, A1 = 0.f;
    #pragma unroll
    for (int sp = 0; sp < NSPLIT; sp++) {
        const float4* pp = &g_part[sp * TOK + idx];
        float4 p;
        asm volatile("ld.global.cg.v4.f32 {%0,%1,%2,%3}, [%4];"
                     : "=f"(p.x), "=f"(p.y), "=f"(p.z), "=f"(p.w) : "l"(pp));
        lt += p.x; A0 += p.y; A1 += p.z;
    }
    float inv = 1.0f / lt;
    float c0 = A0 * inv, c1 = A1 * inv;

    __syncthreads();   // sA/sO/sWu ready

    // u = ctx @ Wu + bu + x
    float u[16];
    const float4* xp = reinterpret_cast<const float4*>(x + idx * DD);
    #pragma unroll
    for (int c4 = 0; c4 < 4; c4++) {
        float4 v = xp[c4];
        float xe[4] = {v.x, v.y, v.z, v.w};
        #pragma unroll
        for (int j = 0; j < 4; j++) {
            int i = c4 * 4 + j;
            u[i] = fmaf(c0, sWu[i], fmaf(c1, sWu[16 + i], sbu[i])) + xe[j];
        }
    }

    // LN stats of u
    float su = 0.f, s2 = 0.f;
    #pragma unroll
    for (int i = 0; i < 16; i++) { su += u[i]; s2 = fmaf(u[i], u[i], s2); }
    float mu = su * (1.0f / 16.0f);
    float r  = rsqrtf(fmaf(-mu, mu, s2 * (1.0f / 16.0f)) + 1e-5f);

    // f = r*(u@A' - mu*csA) + bA
    float f[16];
    {
        float acc[16];
        #pragma unroll
        for (int j = 0; j < 16; j++) acc[j] = 0.f;
        #pragma unroll
        for (int i = 0; i < 16; i++) {
            float hv = u[i];
            const float4* wr = reinterpret_cast<const float4*>(sA + i * 16);
            #pragma unroll
            for (int j4 = 0; j4 < 4; j4++) {
                float4 w = wr[j4];
                acc[4*j4+0] = fmaf(hv, w.x, acc[4*j4+0]);
                acc[4*j4+1] = fmaf(hv, w.y, acc[4*j4+1]);
                acc[4*j4+2] = fmaf(hv, w.z, acc[4*j4+2]);
                acc[4*j4+3] = fmaf(hv, w.w, acc[4*j4+3]);
            }
        }
        #pragma unroll
        for (int j = 0; j < 16; j++)
            f[j] = fmaf(r, fmaf(-mu, scsA[j], acc[j]), sbA[j]);
    }

    // LN stats of f
    float sf = 0.f, sf2 = 0.f;
    #pragma unroll
    for (int i = 0; i < 16; i++) { sf += f[i]; sf2 = fmaf(f[i], f[i], sf2); }
    float mu2 = sf * (1.0f / 16.0f);
    float r2  = rsqrtf(fmaf(-mu2, mu2, sf2 * (1.0f / 16.0f)) + 1e-5f);

    // out = r2*(f@O' - mu2*csO) + bO
    float o[16];
    {
        float acc[16];
        #pragma unroll
        for (int j = 0; j < 16; j++) acc[j] = 0.f;
        #pragma unroll
        for (int i = 0; i < 16; i++) {
            float hv = f[i];
            const float4* wr = reinterpret_cast<const float4*>(sO + i * 16);
            #pragma unroll
            for (int j4 = 0; j4 < 4; j4++) {
                float4 w = wr[j4];
                acc[4*j4+0] = fmaf(hv, w.x, acc[4*j4+0]);
                acc[4*j4+1] = fmaf(hv, w.y, acc[4*j4+1]);
                acc[4*j4+2] = fmaf(hv, w.z, acc[4*j4+2]);
                acc[4*j4+3] = fmaf(hv, w.w, acc[4*j4+3]);
            }
        }
        #pragma unroll
        for (int j = 0; j < 16; j++)
            o[j] = fmaf(r2, fmaf(-mu2, scsO[j], acc[j]), sbO[j]);
    }

    float4* op = reinterpret_cast<float4*>(out + idx * DD);
    #pragma unroll
    for (int c4 = 0; c4 < 4; c4++)
        op[c4] = make_float4(o[4*c4+0], o[4*c4+1], o[4*c4+2], o[4*c4+3]);
}

// ---------------------------------------------------------------------------
extern "C" void kernel_launch(void* const* d_in, const int* in_sizes, int n_in,
                              void* d_out, int out_size)
{
    const float* x    = (const float*)d_in[0];
    const float* Wq   = (const float*)d_in[1];
    const float* bq   = (const float*)d_in[2];
    const float* Wk   = (const float*)d_in[3];
    const float* bk   = (const float*)d_in[4];
    const float* Wv   = (const float*)d_in[5];
    const float* bv   = (const float*)d_in[6];
    const float* Wu   = (const float*)d_in[7];
    const float* bu   = (const float*)d_in[8];
    const float* ln_g = (const float*)d_in[9];
    const float* ln_b = (const float*)d_in[10];
    const float* W1   = (const float*)d_in[11];
    const float* b1   = (const float*)d_in[12];
    const float* W2   = (const float*)d_in[13];
    const float* b2   = (const float*)d_in[14];
    const float* W3   = (const float*)d_in[15];
    const float* b3   = (const float*)d_in[16];
    const float* Wo   = (const float*)d_in[17];
    const float* bo   = (const float*)d_in[18];
    float* out = (float*)d_out;

    qkv_precomp_kernel<<<TOK / 256 + 1, 256>>>(x, Wq, bq, Wk, bk, Wv, bv,
                                               W1, b1, W2, b2, W3, b3,
                                               ln_g, ln_b, Wo, bo);

    dim3 agrid(4, NSPLIT, BB);
    attn_fused_kernel<<<agrid, 256>>>(x, Wu, bu, out);
}

// round 9
// speedup vs baseline: 1.0554x; 1.0554x over previous
#include <cuda_runtime.h>

#define BB 64
#define SS 1024
#define DD 16
#define NSPLIT 4
#define TOK (BB * SS)

// Scratch (allocation-free rule: __device__ globals)
__device__ float4 g_part[NSPLIT * TOK]; // per-split partial (l, a0, a1, 0)
__device__ float2 g_q[TOK];             // q pre-scaled by 0.25*log2(e)
__device__ float4 g_kv[TOK];            // (k0,k1,v0,v1)
__device__ float  g_A[256];             // diag(g) @ (W1W2W3 + I)
__device__ float  g_csA[16];            // column sums of g_A
__device__ float  g_bA[16];             // b @ (W1W2W3+I) + bc
__device__ float  g_O[256];             // diag(g) @ Wo
__device__ float  g_csO[16];            // column sums of g_O
__device__ float  g_bO[16];             // b @ Wo + bo

__device__ __forceinline__ float ex2_approx(float x) {
    float y;
    asm("ex2.approx.f32 %0, %1;" : "=f"(y) : "f"(x));
    return y;
}

// ---------------------------------------------------------------------------
// Kernel 1: QKV projection, 2 threads per token (k-dim split by 8).
// Doubles warps in flight (latency/BW) with unchanged DRAM traffic.
// Last block (blockIdx.x == TOK*2/256) does the epilogue weight folds.
// ---------------------------------------------------------------------------
__global__ void __launch_bounds__(256)
qkv_precomp_kernel(const float* __restrict__ x,
                   const float* __restrict__ Wq, const float* __restrict__ bq,
                   const float* __restrict__ Wk, const float* __restrict__ bk,
                   const float* __restrict__ Wv, const float* __restrict__ bv,
                   const float* __restrict__ W1, const float* __restrict__ b1,
                   const float* __restrict__ W2, const float* __restrict__ b2,
                   const float* __restrict__ W3, const float* __restrict__ b3,
                   const float* __restrict__ ln_g, const float* __restrict__ ln_b,
                   const float* __restrict__ Wo, const float* __restrict__ bo)
{
    int tid = threadIdx.x;

    if (blockIdx.x == (TOK * 2) / 256) {
        // ------- precompute folded epilogue weights -------
        __shared__ float s1[256], s2[256], s3[256], s12[256];
        __shared__ float sA[256], sAraw[256], sO[256];
        __shared__ float sbp[16], sbc[16], sg[16], sb[16];
        int r = tid >> 4, c = tid & 15;
        s1[tid] = W1[tid]; s2[tid] = W2[tid]; s3[tid] = W3[tid];
        if (tid < 16) { sg[tid] = ln_g[tid]; sb[tid] = ln_b[tid]; }
        __syncthreads();

        float acc = 0.f;
        #pragma unroll
        for (int k = 0; k < 16; k++) acc = fmaf(s1[r*16+k], s2[k*16+c], acc);
        s12[tid] = acc;
        if (tid < 16) {                 // b1@W2 + b2
            float t = b2[tid];
            #pragma unroll
            for (int k = 0; k < 16; k++) t = fmaf(b1[k], s2[k*16+tid], t);
            sbp[tid] = t;
        }
        __syncthreads();

        float w123 = 0.f;
        #pragma unroll
        for (int k = 0; k < 16; k++) w123 = fmaf(s12[r*16+k], s3[k*16+c], w123);
        float A = w123 + (r == c ? 1.0f : 0.0f);   // residual folded in
        sAraw[tid] = A;
        sA[tid] = sg[r] * A;
        sO[tid] = sg[r] * Wo[tid];
        if (tid < 16) {                 // bc = (b1@W2+b2)@W3 + b3
            float t = b3[tid];
            #pragma unroll
            for (int k = 0; k < 16; k++) t = fmaf(sbp[k], s3[k*16+tid], t);
            sbc[tid] = t;
        }
        __syncthreads();

        g_A[tid] = sA[tid];
        g_O[tid] = sO[tid];
        if (tid < 16) {
            float cs = 0.f, bb = sbc[tid];
            float cso = 0.f, bb2 = bo[tid];
            #pragma unroll
            for (int i = 0; i < 16; i++) {
                cs  += sA[i*16+tid];
                bb   = fmaf(sb[i], sAraw[i*16+tid], bb);
                cso += sO[i*16+tid];
                bb2  = fmaf(sb[i], Wo[i*16+tid], bb2);
            }
            g_csA[tid] = cs;  g_bA[tid] = bb;
            g_csO[tid] = cso; g_bO[tid] = bb2;
        }
        return;
    }

    // ------- QKV projection, half-row per thread -------
    __shared__ float sw[102];   // Wq[32] Wk[32] Wv[32] bq bk bv
    if (tid < 32)        sw[tid] = Wq[tid];
    else if (tid < 64)   sw[tid] = Wk[tid - 32];
    else if (tid < 96)   sw[tid] = Wv[tid - 64];
    else if (tid < 98)   sw[tid] = bq[tid - 96];
    else if (tid < 100)  sw[tid] = bk[tid - 98];
    else if (tid < 102)  sw[tid] = bv[tid - 100];
    __syncthreads();

    int g    = blockIdx.x * 256 + tid;
    int idx  = g >> 1;
    int half = g & 1;

    const float4* xp = reinterpret_cast<const float4*>(x + idx * DD + half * 8);
    float4 va = xp[0], vb = xp[1];
    float xe[8] = {va.x, va.y, va.z, va.w, vb.x, vb.y, vb.z, vb.w};

    float q0 = 0.f, q1 = 0.f, k0 = 0.f, k1 = 0.f, v0 = 0.f, v1 = 0.f;
    #pragma unroll
    for (int j = 0; j < 8; j++) {
        int i = half * 8 + j;
        float xi = xe[j];
        q0 = fmaf(xi, sw[i*2+0],    q0);
        q1 = fmaf(xi, sw[i*2+1],    q1);
        k0 = fmaf(xi, sw[32+i*2+0], k0);
        k1 = fmaf(xi, sw[32+i*2+1], k1);
        v0 = fmaf(xi, sw[64+i*2+0], v0);
        v1 = fmaf(xi, sw[64+i*2+1], v1);
    }
    // Combine halves (paired lanes)
    q0 += __shfl_xor_sync(0xFFFFFFFFu, q0, 1);
    q1 += __shfl_xor_sync(0xFFFFFFFFu, q1, 1);
    k0 += __shfl_xor_sync(0xFFFFFFFFu, k0, 1);
    k1 += __shfl_xor_sync(0xFFFFFFFFu, k1, 1);
    v0 += __shfl_xor_sync(0xFFFFFFFFu, v0, 1);
    v1 += __shfl_xor_sync(0xFFFFFFFFu, v1, 1);

    const float SC = 0.25f * 1.4426950408889634f;
    if (half == 0) {
        g_q[idx] = make_float2((q0 + sw[96]) * SC, (q1 + sw[97]) * SC);
    } else {
        g_kv[idx] = make_float4(k0 + sw[98], k1 + sw[99],
                                v0 + sw[100], v1 + sw[101]);
    }
}

// ---------------------------------------------------------------------------
// Kernel 2: attention, 4-way KV block split, 2 q-tokens per thread.
// Grid (2, NSPLIT, BB), 256 threads. One LDS.128 feeds 12 math ops.
// ---------------------------------------------------------------------------
__global__ void __launch_bounds__(256)
attn_kernel()
{
    __shared__ float4 skv[256];   // KV quarter (4 KB)

    int tid   = threadIdx.x;
    int b     = blockIdx.z;
    int split = blockIdx.y;
    int chunk = blockIdx.x;

    skv[tid] = g_kv[b * SS + split * 256 + tid];
    __syncthreads();

    int idx0 = b * SS + chunk * 512 + tid;     // token A
    int idx1 = idx0 + 256;                     // token B
    float2 qa = g_q[idx0];
    float2 qb = g_q[idx1];

    float l0 = 0.f, a00 = 0.f, a01 = 0.f;
    float l1 = 0.f, a10 = 0.f, a11 = 0.f;

    #pragma unroll 8
    for (int t = 0; t < 256; t++) {
        float4 kv = skv[t];
        float d0 = fmaf(qa.y, kv.y, qa.x * kv.x);
        float d1 = fmaf(qb.y, kv.y, qb.x * kv.x);
        float p0 = ex2_approx(d0);
        float p1 = ex2_approx(d1);
        l0 += p0;                    l1 += p1;
        a00 = fmaf(p0, kv.z, a00);   a10 = fmaf(p1, kv.z, a10);
        a01 = fmaf(p0, kv.w, a01);   a11 = fmaf(p1, kv.w, a11);
    }

    g_part[split * TOK + idx0] = make_float4(l0, a00, a01, 0.f);
    g_part[split * TOK + idx1] = make_float4(l1, a10, a11, 0.f);
}

// ---------------------------------------------------------------------------
// Kernel 3: epilogue, 2 lanes per token (131072 threads).
// Each lane: full u (local LN1 stats, no shfl), half of each matmul,
// one 8-value f-exchange. LN-folded weights as before.
// ---------------------------------------------------------------------------
__global__ void __launch_bounds__(256)
epilogue_kernel(const float* __restrict__ x,
                const float* __restrict__ Wu, const float* __restrict__ bu,
                float* __restrict__ out)
{
    __shared__ __align__(16) float sA[256], sO[256], sWu[32];
    __shared__ float sbu[16], scsA[16], sbA[16], scsO[16], sbO[16];

    int tid   = threadIdx.x;
    int token = blockIdx.x * 128 + (tid >> 1);
    int half  = tid & 1;
    int hb    = half * 8;

    sA[tid] = g_A[tid]; sO[tid] = g_O[tid];
    if (tid < 32) sWu[tid] = Wu[tid];
    if (tid < 16) {
        sbu[tid] = bu[tid];
        scsA[tid] = g_csA[tid]; sbA[tid] = g_bA[tid];
        scsO[tid] = g_csO[tid]; sbO[tid] = g_bO[tid];
    }
    __syncthreads();

    // Combine partials: lane loads 2 splits, pair-xor for the other 2
    float4 pA = g_part[(half * 2 + 0) * TOK + token];
    float4 pB = g_part[(half * 2 + 1) * TOK + token];
    float l  = pA.x + pB.x;
    float a0 = pA.y + pB.y;
    float a1 = pA.z + pB.z;
    l  += __shfl_xor_sync(0xFFFFFFFFu, l, 1);
    a0 += __shfl_xor_sync(0xFFFFFFFFu, a0, 1);
    a1 += __shfl_xor_sync(0xFFFFFFFFu, a1, 1);
    float inv = 1.0f / l;
    float c0 = a0 * inv, c1 = a1 * inv;

    // Full u per lane (dup math, zero shfl for LN1)
    float u[16];
    const float4* xp = reinterpret_cast<const float4*>(x + token * DD);
    #pragma unroll
    for (int c4 = 0; c4 < 4; c4++) {
        float4 v = xp[c4];
        float xe[4] = {v.x, v.y, v.z, v.w};
        #pragma unroll
        for (int j = 0; j < 4; j++) {
            int i = c4 * 4 + j;
            u[i] = fmaf(c0, sWu[i], fmaf(c1, sWu[16 + i], sbu[i])) + xe[j];
        }
    }

    float su = 0.f, s2 = 0.f;
    #pragma unroll
    for (int i = 0; i < 16; i++) { su += u[i]; s2 = fmaf(u[i], u[i], s2); }
    float mu = su * (1.0f / 16.0f);
    float r  = rsqrtf(fmaf(-mu, mu, s2 * (1.0f / 16.0f)) + 1e-5f);

    // mm1 half: f_loc[j] for columns hb..hb+7
    float acc[8];
    #pragma unroll
    for (int j = 0; j < 8; j++) acc[j] = 0.f;
    #pragma unroll
    for (int i = 0; i < 16; i++) {
        float hv = u[i];
        const float4* wr = reinterpret_cast<const float4*>(sA + i * 16 + hb);
        float4 w0 = wr[0], w1 = wr[1];
        acc[0] = fmaf(hv, w0.x, acc[0]);
        acc[1] = fmaf(hv, w0.y, acc[1]);
        acc[2] = fmaf(hv, w0.z, acc[2]);
        acc[3] = fmaf(hv, w0.w, acc[3]);
        acc[4] = fmaf(hv, w1.x, acc[4]);
        acc[5] = fmaf(hv, w1.y, acc[5]);
        acc[6] = fmaf(hv, w1.z, acc[6]);
        acc[7] = fmaf(hv, w1.w, acc[7]);
    }
    float floc[8];
    #pragma unroll
    for (int j = 0; j < 8; j++)
        floc[j] = fmaf(r, fmaf(-mu, scsA[hb + j], acc[j]), sbA[hb + j]);

    // Exchange halves -> full f per lane
    float frem[8];
    #pragma unroll
    for (int j = 0; j < 8; j++)
        frem[j] = __shfl_xor_sync(0xFFFFFFFFu, floc[j], 1);
    float ff[16];
    #pragma unroll
    for (int j = 0; j < 8; j++) {
        ff[j]     = half ? frem[j] : floc[j];
        ff[8 + j] = half ? floc[j] : frem[j];
    }

    float sf = 0.f, sf2 = 0.f;
    #pragma unroll
    for (int i = 0; i < 16; i++) { sf += ff[i]; sf2 = fmaf(ff[i], ff[i], sf2); }
    float mu2 = sf * (1.0f / 16.0f);
    float r2  = rsqrtf(fmaf(-mu2, mu2, sf2 * (1.0f / 16.0f)) + 1e-5f);

    // mm2 half
    float acc2[8];
    #pragma unroll
    for (int j = 0; j < 8; j++) acc2[j] = 0.f;
    #pragma unroll
    for (int i = 0; i < 16; i++) {
        float hv = ff[i];
        const float4* wr = reinterpret_cast<const float4*>(sO + i * 16 + hb);
        float4 w0 = wr[0], w1 = wr[1];
        acc2[0] = fmaf(hv, w0.x, acc2[0]);
        acc2[1] = fmaf(hv, w0.y, acc2[1]);
        acc2[2] = fmaf(hv, w0.z, acc2[2]);
        acc2[3] = fmaf(hv, w0.w, acc2[3]);
        acc2[4] = fmaf(hv, w1.x, acc2[4]);
        acc2[5] = fmaf(hv, w1.y, acc2[5]);
        acc2[6] = fmaf(hv, w1.z, acc2[6]);
        acc2[7] = fmaf(hv, w1.w, acc2[7]);
    }
    float o[8];
    #pragma unroll
    for (int j = 0; j < 8; j++)
        o[j] = fmaf(r2, fmaf(-mu2, scsO[hb + j], acc2[j]), sbO[hb + j]);

    float4* op = reinterpret_cast<float4*>(out + token * DD + hb);
    op[0] = make_float4(o[0], o[1], o[2], o[3]);
    op[1] = make_float4(o[4], o[5], o[6], o[7]);
}

// ---------------------------------------------------------------------------
extern "C" void kernel_launch(void* const* d_in, const int* in_sizes, int n_in,
                              void* d_out, int out_size)
{
    const float* x    = (const float*)d_in[0];
    const float* Wq   = (const float*)d_in[1];
    const float* bq   = (const float*)d_in[2];
    const float* Wk   = (const float*)d_in[3];
    const float* bk   = (const float*)d_in[4];
    const float* Wv   = (const float*)d_in[5];
    const float* bv   = (const float*)d_in[6];
    const float* Wu   = (const float*)d_in[7];
    const float* bu   = (const float*)d_in[8];
    const float* ln_g = (const float*)d_in[9];
    const float* ln_b = (const float*)d_in[10];
    const float* W1   = (const float*)d_in[11];
    const float* b1   = (const float*)d_in[12];
    const float* W2   = (const float*)d_in[13];
    const float* b2   = (const float*)d_in[14];
    const float* W3   = (const float*)d_in[15];
    const float* b3   = (const float*)d_in[16];
    const float* Wo   = (const float*)d_in[17];
    const float* bo   = (const float*)d_in[18];
    float* out = (float*)d_out;

    qkv_precomp_kernel<<<(TOK * 2) / 256 + 1, 256>>>(x, Wq, bq, Wk, bk, Wv, bv,
                                                     W1, b1, W2, b2, W3, b3,
                                                     ln_g, ln_b, Wo, bo);

    dim3 agrid(2, NSPLIT, BB);
    attn_kernel<<<agrid, 256>>>();

    epilogue_kernel<<<TOK / 128, 256>>>(x, Wu, bu, out);
}

// round 10
// speedup vs baseline: 1.1152x; 1.0567x over previous
#include <cuda_runtime.h>

#define BB 64
#define SS 1024
#define DD 16
#define NSPLIT 4
#define TOK (BB * SS)

// Scratch (allocation-free rule: __device__ globals)
__device__ float4 g_part[NSPLIT * TOK]; // per-split partial (l, a0, a1, 0)
__device__ float2 g_q[TOK];             // q pre-scaled by 0.25*log2(e)
__device__ float4 g_kv[TOK];            // (k0,k1,v0,v1)
__device__ float  g_A[256];             // diag(g) @ (W1W2W3 + I)
__device__ float  g_csA[16];            // column sums of g_A
__device__ float  g_bA[16];             // b @ (W1W2W3+I) + bc
__device__ float  g_O[256];             // diag(g) @ Wo
__device__ float  g_csO[16];            // column sums of g_O
__device__ float  g_bO[16];             // b @ Wo + bo

__device__ __forceinline__ float ex2_approx(float x) {
    float y;
    asm("ex2.approx.f32 %0, %1;" : "=f"(y) : "f"(x));
    return y;
}

// ---------------------------------------------------------------------------
// Kernel 1: QKV projection, 1 thread/token (measured-best form), with x
// loads hoisted above the smem weight prologue to overlap DRAM latency.
// Last block does the epilogue weight folds.
// ---------------------------------------------------------------------------
__global__ void __launch_bounds__(256)
qkv_precomp_kernel(const float* __restrict__ x,
                   const float* __restrict__ Wq, const float* __restrict__ bq,
                   const float* __restrict__ Wk, const float* __restrict__ bk,
                   const float* __restrict__ Wv, const float* __restrict__ bv,
                   const float* __restrict__ W1, const float* __restrict__ b1,
                   const float* __restrict__ W2, const float* __restrict__ b2,
                   const float* __restrict__ W3, const float* __restrict__ b3,
                   const float* __restrict__ ln_g, const float* __restrict__ ln_b,
                   const float* __restrict__ Wo, const float* __restrict__ bo)
{
    int tid = threadIdx.x;

    if (blockIdx.x == TOK / 256) {
        // ------- precompute folded epilogue weights -------
        __shared__ float s1[256], s2[256], s3[256], s12[256];
        __shared__ float sA[256], sAraw[256], sO[256];
        __shared__ float sbp[16], sbc[16], sg[16], sb[16];
        int r = tid >> 4, c = tid & 15;
        s1[tid] = W1[tid]; s2[tid] = W2[tid]; s3[tid] = W3[tid];
        if (tid < 16) { sg[tid] = ln_g[tid]; sb[tid] = ln_b[tid]; }
        __syncthreads();

        float acc = 0.f;
        #pragma unroll
        for (int k = 0; k < 16; k++) acc = fmaf(s1[r*16+k], s2[k*16+c], acc);
        s12[tid] = acc;
        if (tid < 16) {                 // b1@W2 + b2
            float t = b2[tid];
            #pragma unroll
            for (int k = 0; k < 16; k++) t = fmaf(b1[k], s2[k*16+tid], t);
            sbp[tid] = t;
        }
        __syncthreads();

        float w123 = 0.f;
        #pragma unroll
        for (int k = 0; k < 16; k++) w123 = fmaf(s12[r*16+k], s3[k*16+c], w123);
        float A = w123 + (r == c ? 1.0f : 0.0f);   // residual folded in
        sAraw[tid] = A;
        sA[tid] = sg[r] * A;
        sO[tid] = sg[r] * Wo[tid];
        if (tid < 16) {                 // bc = (b1@W2+b2)@W3 + b3
            float t = b3[tid];
            #pragma unroll
            for (int k = 0; k < 16; k++) t = fmaf(sbp[k], s3[k*16+tid], t);
            sbc[tid] = t;
        }
        __syncthreads();

        g_A[tid] = sA[tid];
        g_O[tid] = sO[tid];
        if (tid < 16) {
            float cs = 0.f, bb = sbc[tid];
            float cso = 0.f, bb2 = bo[tid];
            #pragma unroll
            for (int i = 0; i < 16; i++) {
                cs  += sA[i*16+tid];
                bb   = fmaf(sb[i], sAraw[i*16+tid], bb);
                cso += sO[i*16+tid];
                bb2  = fmaf(sb[i], Wo[i*16+tid], bb2);
            }
            g_csA[tid] = cs;  g_bA[tid] = bb;
            g_csO[tid] = cso; g_bO[tid] = bb2;
        }
        return;
    }

    // ------- QKV projection -------
    int idx = blockIdx.x * 256 + tid;

    // Hoisted x loads: 4 independent LDG.128 in flight before the prologue
    const float4* xp = reinterpret_cast<const float4*>(x + idx * DD);
    float4 xv0 = xp[0], xv1 = xp[1], xv2 = xp[2], xv3 = xp[3];

    __shared__ float sw[102];
    if (tid < 32)        sw[tid] = Wq[tid];
    else if (tid < 64)   sw[tid] = Wk[tid - 32];
    else if (tid < 96)   sw[tid] = Wv[tid - 64];
    else if (tid < 98)   sw[tid] = bq[tid - 96];
    else if (tid < 100)  sw[tid] = bk[tid - 98];
    else if (tid < 102)  sw[tid] = bv[tid - 100];
    __syncthreads();

    float xv[16] = {xv0.x, xv0.y, xv0.z, xv0.w, xv1.x, xv1.y, xv1.z, xv1.w,
                    xv2.x, xv2.y, xv2.z, xv2.w, xv3.x, xv3.y, xv3.z, xv3.w};

    float q0 = sw[96], q1 = sw[97];
    float k0 = sw[98], k1 = sw[99];
    float v0 = sw[100], v1 = sw[101];
    #pragma unroll
    for (int i = 0; i < 16; i++) {
        float xi = xv[i];
        q0 = fmaf(xi, sw[i*2+0],    q0);
        q1 = fmaf(xi, sw[i*2+1],    q1);
        k0 = fmaf(xi, sw[32+i*2+0], k0);
        k1 = fmaf(xi, sw[32+i*2+1], k1);
        v0 = fmaf(xi, sw[64+i*2+0], v0);
        v1 = fmaf(xi, sw[64+i*2+1], v1);
    }

    const float SC = 0.25f * 1.4426950408889634f;  // fold scale + log2e into Q
    g_q[idx]  = make_float2(q0 * SC, q1 * SC);
    g_kv[idx] = make_float4(k0, k1, v0, v1);
}

// ---------------------------------------------------------------------------
// Kernel 2: attention, 4-way KV block split, 2 q-tokens per thread.
// Grid (2, NSPLIT, BB), 256 threads. One LDS.128 feeds 12 math ops.
// Global loads hoisted above the smem store + barrier.
// ---------------------------------------------------------------------------
__global__ void __launch_bounds__(256)
attn_kernel()
{
    __shared__ float4 skv[256];   // KV quarter (4 KB)

    int tid   = threadIdx.x;
    int b     = blockIdx.z;
    int split = blockIdx.y;
    int chunk = blockIdx.x;

    int idx0 = b * SS + chunk * 512 + tid;     // token A
    int idx1 = idx0 + 256;                     // token B

    // Hoist all three independent global loads
    float4 kvrow = g_kv[b * SS + split * 256 + tid];
    float2 qa = g_q[idx0];
    float2 qb = g_q[idx1];

    skv[tid] = kvrow;
    __syncthreads();

    float l0 = 0.f, a00 = 0.f, a01 = 0.f;
    float l1 = 0.f, a10 = 0.f, a11 = 0.f;

    #pragma unroll 8
    for (int t = 0; t < 256; t++) {
        float4 kv = skv[t];
        float d0 = fmaf(qa.y, kv.y, qa.x * kv.x);
        float d1 = fmaf(qb.y, kv.y, qb.x * kv.x);
        float p0 = ex2_approx(d0);
        float p1 = ex2_approx(d1);
        l0 += p0;                    l1 += p1;
        a00 = fmaf(p0, kv.z, a00);   a10 = fmaf(p1, kv.z, a10);
        a01 = fmaf(p0, kv.w, a01);   a11 = fmaf(p1, kv.w, a11);
    }

    g_part[split * TOK + idx0] = make_float4(l0, a00, a01, 0.f);
    g_part[split * TOK + idx1] = make_float4(l1, a10, a11, 0.f);
}

// ---------------------------------------------------------------------------
// Kernel 3: epilogue, 1 thread per token (measured-best form), LN-folded
// weights, no shfl. Partial + x loads hoisted above the smem prologue.
// ---------------------------------------------------------------------------
__global__ void __launch_bounds__(256)
epilogue_kernel(const float* __restrict__ x,
                const float* __restrict__ Wu, const float* __restrict__ bu,
                float* __restrict__ out)
{
    __shared__ __align__(16) float sA[256], sO[256], sWu[32];
    __shared__ float sbu[16], scsA[16], sbA[16], scsO[16], sbO[16];

    int tid = threadIdx.x;
    int idx = blockIdx.x * 256 + tid;

    // Hoisted: 4 partial loads + 4 x loads, 8 LDG.128 in flight
    float4 p0 = g_part[0 * TOK + idx];
    float4 p1 = g_part[1 * TOK + idx];
    float4 p2 = g_part[2 * TOK + idx];
    float4 p3 = g_part[3 * TOK + idx];
    const float4* xp = reinterpret_cast<const float4*>(x + idx * DD);
    float4 xv0 = xp[0], xv1 = xp[1], xv2 = xp[2], xv3 = xp[3];

    sA[tid] = g_A[tid]; sO[tid] = g_O[tid];
    if (tid < 32) sWu[tid] = Wu[tid];
    if (tid < 16) {
        sbu[tid] = bu[tid];
        scsA[tid] = g_csA[tid]; sbA[tid] = g_bA[tid];
        scsO[tid] = g_csO[tid]; sbO[tid] = g_bO[tid];
    }
    __syncthreads();

    float l  = p0.x + p1.x + p2.x + p3.x;
    float a0 = p0.y + p1.y + p2.y + p3.y;
    float a1 = p0.z + p1.z + p2.z + p3.z;
    float inv = 1.0f / l;
    float c0 = a0 * inv, c1 = a1 * inv;

    float xr[16] = {xv0.x, xv0.y, xv0.z, xv0.w, xv1.x, xv1.y, xv1.z, xv1.w,
                    xv2.x, xv2.y, xv2.z, xv2.w, xv3.x, xv3.y, xv3.z, xv3.w};

    // u = ctx @ Wu + bu + x
    float u[16];
    #pragma unroll
    for (int i = 0; i < 16; i++)
        u[i] = fmaf(c0, sWu[i], fmaf(c1, sWu[16 + i], sbu[i])) + xr[i];

    // LN stats of u
    float su = 0.f, s2 = 0.f;
    #pragma unroll
    for (int i = 0; i < 16; i++) { su += u[i]; s2 = fmaf(u[i], u[i], s2); }
    float mu = su * (1.0f / 16.0f);
    float r  = rsqrtf(fmaf(-mu, mu, s2 * (1.0f / 16.0f)) + 1e-5f);

    // f = r*(u@A' - mu*csA) + bA
    float f[16];
    {
        float acc[16];
        #pragma unroll
        for (int j = 0; j < 16; j++) acc[j] = 0.f;
        #pragma unroll
        for (int i = 0; i < 16; i++) {
            float hv = u[i];
            const float4* wr = reinterpret_cast<const float4*>(sA + i * 16);
            #pragma unroll
            for (int j4 = 0; j4 < 4; j4++) {
                float4 w = wr[j4];
                acc[4*j4+0] = fmaf(hv, w.x, acc[4*j4+0]);
                acc[4*j4+1] = fmaf(hv, w.y, acc[4*j4+1]);
                acc[4*j4+2] = fmaf(hv, w.z, acc[4*j4+2]);
                acc[4*j4+3] = fmaf(hv, w.w, acc[4*j4+3]);
            }
        }
        #pragma unroll
        for (int j = 0; j < 16; j++)
            f[j] = fmaf(r, fmaf(-mu, scsA[j], acc[j]), sbA[j]);
    }

    // LN stats of f
    float sf = 0.f, sf2 = 0.f;
    #pragma unroll
    for (int i = 0; i < 16; i++) { sf += f[i]; sf2 = fmaf(f[i], f[i], sf2); }
    float mu2 = sf * (1.0f / 16.0f);
    float r2  = rsqrtf(fmaf(-mu2, mu2, sf2 * (1.0f / 16.0f)) + 1e-5f);

    // out = r2*(f@O' - mu2*csO) + bO
    float o[16];
    {
        float acc[16];
        #pragma unroll
        for (int j = 0; j < 16; j++) acc[j] = 0.f;
        #pragma unroll
        for (int i = 0; i < 16; i++) {
            float hv = f[i];
            const float4* wr = reinterpret_cast<const float4*>(sO + i * 16);
            #pragma unroll
            for (int j4 = 0; j4 < 4; j4++) {
                float4 w = wr[j4];
                acc[4*j4+0] = fmaf(hv, w.x, acc[4*j4+0]);
                acc[4*j4+1] = fmaf(hv, w.y, acc[4*j4+1]);
                acc[4*j4+2] = fmaf(hv, w.z, acc[4*j4+2]);
                acc[4*j4+3] = fmaf(hv, w.w, acc[4*j4+3]);
            }
        }
        #pragma unroll
        for (int j = 0; j < 16; j++)
            o[j] = fmaf(r2, fmaf(-mu2, scsO[j], acc[j]), sbO[j]);
    }

    float4* op = reinterpret_cast<float4*>(out + idx * DD);
    #pragma unroll
    for (int c4 = 0; c4 < 4; c4++)
        op[c4] = make_float4(o[4*c4+0], o[4*c4+1], o[4*c4+2], o[4*c4+3]);
}

// ---------------------------------------------------------------------------
extern "C" void kernel_launch(void* const* d_in, const int* in_sizes, int n_in,
                              void* d_out, int out_size)
{
    const float* x    = (const float*)d_in[0];
    const float* Wq   = (const float*)d_in[1];
    const float* bq   = (const float*)d_in[2];
    const float* Wk   = (const float*)d_in[3];
    const float* bk   = (const float*)d_in[4];
    const float* Wv   = (const float*)d_in[5];
    const float* bv   = (const float*)d_in[6];
    const float* Wu   = (const float*)d_in[7];
    const float* bu   = (const float*)d_in[8];
    const float* ln_g = (const float*)d_in[9];
    const float* ln_b = (const float*)d_in[10];
    const float* W1   = (const float*)d_in[11];
    const float* b1   = (const float*)d_in[12];
    const float* W2   = (const float*)d_in[13];
    const float* b2   = (const float*)d_in[14];
    const float* W3   = (const float*)d_in[15];
    const float* b3   = (const float*)d_in[16];
    const float* Wo   = (const float*)d_in[17];
    const float* bo   = (const float*)d_in[18];
    float* out = (float*)d_out;

    qkv_precomp_kernel<<<TOK / 256 + 1, 256>>>(x, Wq, bq, Wk, bk, Wv, bv,
                                               W1, b1, W2, b2, W3, b3,
                                               ln_g, ln_b, Wo, bo);

    dim3 agrid(2, NSPLIT, BB);
    attn_kernel<<<agrid, 256>>>();

    epilogue_kernel<<<TOK / 256, 256>>>(x, Wu, bu, out);
}